// round 1
// baseline (speedup 1.0000x reference)
#include <cuda_runtime.h>

// FASTMultiHeadAttention: degree-2 Taylor attention with RPE.
// B=2,H=8 (bh=16), N=1024, D=64. fp32 throughout.
//
// z_ij = q_i . k_j + q_i . rpe[i - j + N - 1]
// s    = 1 + z + 0.5 z^2
// o_i  = sum_j s_ij v_j / sum_j s_ij

constexpr int NSEQ = 1024;
constexpr int DD   = 64;
constexpr int BI   = 128;   // i-tile per CTA
constexpr int BJ   = 64;    // j-tile per step

// smem strides (floats). Transposed arrays use rotation swizzle col += 4*(d>>2).
constexpr int QS_STR = 192;  // Q^T: [64 d][128 + rot<=60]
constexpr int KS_STR = 128;  // K^T: [64 d][64 + rot<=60]
constexpr int RS_STR = 256;  // rpe band^T: [64 d][191 + rot<=60]
constexpr int VS_STR = 64;   // V row-major [64 j][64 d]
constexpr int SS_STR = 68;   // S row-major [128 i][64 j] (+4 pad)

constexpr int SM_FLOATS = 64*QS_STR + 64*KS_STR + 64*RS_STR + 64*VS_STR + 128*SS_STR + 128;

__global__ void __launch_bounds__(256, 1)
fast_attn_kernel(const float* __restrict__ q, const float* __restrict__ k,
                 const float* __restrict__ v, const float* __restrict__ rpe,
                 float* __restrict__ out)
{
    extern __shared__ float sm[];
    float* Qs = sm;
    float* Ks = Qs + 64*QS_STR;
    float* Rs = Ks + 64*KS_STR;
    float* Vs = Rs + 64*RS_STR;
    float* Ss = Vs + 64*VS_STR;
    float* Ds = Ss + 128*SS_STR;

    const int bh = blockIdx.y;
    const int i0 = blockIdx.x * BI;
    const int t  = threadIdx.x;
    const int ti = t >> 4;    // 0..15, owns 8 i-rows
    const int tj = t & 15;    // 0..15, owns 4 j-cols (GEMM1) / 4 d-cols (GEMM2)
    const int cb = ti*8 - tj*4 + 60;   // band window base (multiple of 4, in [0,180])

    const float* qb = q + (size_t)bh * NSEQ * DD;
    const float* kb = k + (size_t)bh * NSEQ * DD;
    const float* vb = v + (size_t)bh * NSEQ * DD;

    // ---- load Q tile transposed with rotation swizzle (once) ----
    #pragma unroll
    for (int it = 0; it < 8; ++it) {
        int idx = t + it*256;
        int c  = idx >> 4;        // source row (ii), dest column base
        int c4 = idx & 15;        // d-group
        float4 val = *(const float4*)(qb + (size_t)(i0 + c)*DD + (c4<<2));
        float* dst = Qs + (c4<<2)*QS_STR + c + (c4<<2);
        dst[0*QS_STR] = val.x; dst[1*QS_STR] = val.y;
        dst[2*QS_STR] = val.z; dst[3*QS_STR] = val.w;
    }

    float oacc[8][4];
    float dpart[8];
    #pragma unroll
    for (int i = 0; i < 8; ++i) {
        dpart[i] = 0.f;
        #pragma unroll
        for (int j = 0; j < 4; ++j) oacc[i][j] = 0.f;
    }

    for (int j0 = 0; j0 < NSEQ; j0 += BJ) {
        __syncthreads();   // previous GEMM2 done reading Vs/Ss before overwrite

        // ---- K tile transposed (rotation swizzle) ----
        #pragma unroll
        for (int it = 0; it < 4; ++it) {
            int idx = t + it*256;
            int c = idx >> 4, c4 = idx & 15;
            float4 val = *(const float4*)(kb + (size_t)(j0 + c)*DD + (c4<<2));
            float* dst = Ks + (c4<<2)*KS_STR + c + (c4<<2);
            dst[0*KS_STR] = val.x; dst[1*KS_STR] = val.y;
            dst[2*KS_STR] = val.z; dst[3*KS_STR] = val.w;
        }
        // ---- V tile straight copy ----
        {
            const float4* src = (const float4*)(vb + (size_t)j0*DD);
            float4* dst = (float4*)Vs;
            #pragma unroll
            for (int it = 0; it < 4; ++it) dst[t + it*256] = src[t + it*256];
        }
        // ---- rpe band transposed (191 rows, rotation swizzle) ----
        // r = i - j + 1023; band rows r0..r0+190 with r0 = i0 - j0 + 960,
        // always within [0, 2046] for BI=128.
        {
            int r0 = i0 - j0 + 960;
            #pragma unroll
            for (int it = 0; it < 12; ++it) {
                int idx = t + it*256;
                int c = idx >> 4, c4 = idx & 15;
                if (c < 191) {
                    float4 val = *(const float4*)(rpe + (size_t)(r0 + c)*DD + (c4<<2));
                    float* dst = Rs + (c4<<2)*RS_STR + c + (c4<<2);
                    dst[0*RS_STR] = val.x; dst[1*RS_STR] = val.y;
                    dst[2*RS_STR] = val.z; dst[3*RS_STR] = val.w;
                }
            }
        }
        __syncthreads();

        // ---- GEMM1: z[8][4] = Q (K^T) + fused band term ----
        float zacc[8][4];
        #pragma unroll
        for (int i = 0; i < 8; ++i)
            #pragma unroll
            for (int j = 0; j < 4; ++j) zacc[i][j] = 0.f;

        #pragma unroll 4
        for (int d = 0; d < DD; ++d) {
            const int rot = ((d >> 2) & 15) << 2;
            const float* qrow = Qs + d*QS_STR + rot;
            const float4 a0 = *(const float4*)(qrow + ti*8);
            const float4 a1 = *(const float4*)(qrow + ti*8 + 4);
            const float4 bv = *(const float4*)(Ks + d*KS_STR + rot + tj*4);
            const float* rrow = Rs + d*RS_STR + rot + cb;
            const float4 r0v = *(const float4*)(rrow);
            const float4 r1v = *(const float4*)(rrow + 4);
            const float4 r2v = *(const float4*)(rrow + 8);
            const float a[8]  = {a0.x,a0.y,a0.z,a0.w,a1.x,a1.y,a1.z,a1.w};
            const float b[4]  = {bv.x,bv.y,bv.z,bv.w};
            const float rb[12]= {r0v.x,r0v.y,r0v.z,r0v.w,
                                 r1v.x,r1v.y,r1v.z,r1v.w,
                                 r2v.x,r2v.y,r2v.z,r2v.w};
            #pragma unroll
            for (int ii = 0; ii < 8; ++ii) {
                #pragma unroll
                for (int jj = 0; jj < 4; ++jj) {
                    zacc[ii][jj] = fmaf(a[ii], b[jj],          zacc[ii][jj]);
                    zacc[ii][jj] = fmaf(a[ii], rb[ii + 3 - jj], zacc[ii][jj]);
                }
            }
        }

        // ---- transform s = 1 + z + 0.5 z^2, row-sum partials, stage S ----
        #pragma unroll
        for (int ii = 0; ii < 8; ++ii) {
            float z0 = zacc[ii][0], z1 = zacc[ii][1], z2 = zacc[ii][2], z3 = zacc[ii][3];
            float s0 = fmaf(z0, fmaf(0.5f, z0, 1.0f), 1.0f);
            float s1 = fmaf(z1, fmaf(0.5f, z1, 1.0f), 1.0f);
            float s2 = fmaf(z2, fmaf(0.5f, z2, 1.0f), 1.0f);
            float s3 = fmaf(z3, fmaf(0.5f, z3, 1.0f), 1.0f);
            dpart[ii] += (s0 + s1) + (s2 + s3);
            *(float4*)(Ss + (ti*8 + ii)*SS_STR + tj*4) = make_float4(s0, s1, s2, s3);
        }
        __syncthreads();

        // ---- GEMM2: O[8][4] += S @ V ----
        #pragma unroll 4
        for (int j = 0; j < BJ; ++j) {
            const float4 bv = *(const float4*)(Vs + j*VS_STR + tj*4);
            #pragma unroll
            for (int ii = 0; ii < 8; ++ii) {
                const float av = Ss[(ti*8 + ii)*SS_STR + j];
                oacc[ii][0] = fmaf(av, bv.x, oacc[ii][0]);
                oacc[ii][1] = fmaf(av, bv.y, oacc[ii][1]);
                oacc[ii][2] = fmaf(av, bv.z, oacc[ii][2]);
                oacc[ii][3] = fmaf(av, bv.w, oacc[ii][3]);
            }
        }
    }

    // ---- denominator: reduce dpart across the 16 tj threads (width-16 shuffle) ----
    #pragma unroll
    for (int ii = 0; ii < 8; ++ii) {
        float dsum = dpart[ii];
        #pragma unroll
        for (int off = 8; off > 0; off >>= 1)
            dsum += __shfl_down_sync(0xffffffffu, dsum, off, 16);
        if (tj == 0) Ds[ti*8 + ii] = dsum;
    }
    __syncthreads();

    // ---- epilogue: divide and store ----
    float* ob = out + ((size_t)bh*NSEQ + i0)*DD;
    #pragma unroll
    for (int ii = 0; ii < 8; ++ii) {
        const float inv = 1.0f / Ds[ti*8 + ii];
        float4 ov;
        ov.x = oacc[ii][0]*inv; ov.y = oacc[ii][1]*inv;
        ov.z = oacc[ii][2]*inv; ov.w = oacc[ii][3]*inv;
        *(float4*)(ob + (size_t)(ti*8 + ii)*DD + tj*4) = ov;
    }
}

extern "C" void kernel_launch(void* const* d_in, const int* in_sizes, int n_in,
                              void* d_out, int out_size)
{
    const float* q   = (const float*)d_in[0];
    const float* k   = (const float*)d_in[1];
    const float* v   = (const float*)d_in[2];
    // d_in[3] = drop_noise (unused: dropout=0 in reference)
    const float* rpe = (const float*)d_in[4];
    float* out = (float*)d_out;

    const size_t smem = SM_FLOATS * sizeof(float);   // ~194.5 KB
    cudaFuncSetAttribute(fast_attn_kernel,
                         cudaFuncAttributeMaxDynamicSharedMemorySize, (int)smem);
    dim3 grid(NSEQ / BI, 16);   // 8 i-tiles x 16 bh = 128 CTAs (one wave)
    fast_attn_kernel<<<grid, 256, smem>>>(q, k, v, rpe, out);
}